// round 2
// baseline (speedup 1.0000x reference)
#include <cuda_runtime.h>

#define NN 100000
#define EE 3200000
#define DD 128
#define EPS 1e-5f

// Scratch (allocation-free rule: __device__ globals)
__device__ float g_neigh[NN * DD];   // segment sums
__device__ float g_rst[NN * DD];     // pre-BN activations
__device__ float g_deg[NN];
__device__ float g_colsum[DD];
__device__ float g_colsumsq[DD];
__device__ float g_coefA[DD];
__device__ float g_coefB[DD];

// ---------------------------------------------------------------------------
// K0: zero scratch
// ---------------------------------------------------------------------------
__global__ void zero_kernel() {
    int i = blockIdx.x * blockDim.x + threadIdx.x;
    int stride = gridDim.x * blockDim.x;
    float4 z = make_float4(0.f, 0.f, 0.f, 0.f);
    float4* p = (float4*)g_neigh;
    const int nf4 = NN * DD / 4;
    for (int f = i; f < nf4; f += stride) p[f] = z;
    for (int f = i; f < NN; f += stride) g_deg[f] = 0.f;
    if (i < DD) { g_colsum[i] = 0.f; g_colsumsq[i] = 0.f; }
}

// ---------------------------------------------------------------------------
// K1: edge scatter. One warp per edge (grid-stride), lane = 16B chunk of row.
// red.global.add.v4.f32: no return value, 1/4 the atomic op count.
// NOTE: src/dst are int32 (JAX x64-disabled demotes jnp.int64 -> int32).
// ---------------------------------------------------------------------------
__global__ void scatter_kernel(const float* __restrict__ h,
                               const int* __restrict__ src,
                               const int* __restrict__ dst) {
    int lane = threadIdx.x & 31;
    int warp = (blockIdx.x * blockDim.x + threadIdx.x) >> 5;
    int nwarp = (gridDim.x * blockDim.x) >> 5;
    for (int e = warp; e < EE; e += nwarp) {
        int s = __ldg(&src[e]);
        int d = __ldg(&dst[e]);
        const float4* hrow = (const float4*)(h + (long long)s * DD);
        float4 v = hrow[lane];
        float4* p = ((float4*)(g_neigh + (long long)d * DD)) + lane;
        asm volatile("red.global.add.v4.f32 [%0], {%1,%2,%3,%4};"
                     :: "l"(p), "f"(v.x), "f"(v.y), "f"(v.z), "f"(v.w)
                     : "memory");
        if (lane == 0) atomicAdd(&g_deg[d], 1.0f);
    }
}

// ---------------------------------------------------------------------------
// K2: rst = relu(h @ Ws + neigh @ Wn + b); also accumulate per-column
// sum / sumsq for BatchNorm. Both W matrices in smem (128 KB), 64 rows/block,
// 4x4 register tile per thread.
// ---------------------------------------------------------------------------
#define RB 64   // rows per block
#define TR 32   // rows per tile

__global__ void __launch_bounds__(256, 1)
gemm_kernel(const float* __restrict__ h,
            const float* __restrict__ Wself,
            const float* __restrict__ Wneigh,
            const float* __restrict__ bias) {
    extern __shared__ float sm[];
    float* sWs  = sm;                    // 16384 floats
    float* sWn  = sm + 16384;            // 16384
    float* sh   = sm + 32768;            // TR*128 = 4096
    float* sn   = sm + 32768 + 4096;     // 4096
    float* sred = sm + 32768 + 8192;     // 2*8*128 = 2048
    // total 43008 floats = 172032 bytes

    int t  = threadIdx.x;
    int cg = t & 31;        // column group: cols 4*cg .. 4*cg+3
    int rg = t >> 5;        // row group (warp id): rows 4*rg .. 4*rg+3 in tile
    int c0 = cg * 4;

    // cooperative W load (float4)
    {
        const float4* w1 = (const float4*)Wself;
        const float4* w2 = (const float4*)Wneigh;
        float4* s1 = (float4*)sWs;
        float4* s2 = (float4*)sWn;
        for (int f = t; f < 4096; f += 256) { s1[f] = w1[f]; s2[f] = w2[f]; }
    }

    float4 bv = ((const float4*)bias)[cg];
    float lsum[4] = {0.f, 0.f, 0.f, 0.f};
    float lsq[4]  = {0.f, 0.f, 0.f, 0.f};

    for (int tt = 0; tt < RB / TR; tt++) {
        int row_base = blockIdx.x * RB + tt * TR;
        __syncthreads();   // protect sh/sn from previous tile's readers
        // load h tile and neigh tile (neigh = segsum * 1/max(deg,1))
        for (int f = t; f < TR * 32; f += 256) {   // 1024 float4
            int r  = f >> 5;
            int c4 = f & 31;
            int row = row_base + r;
            float4 hv = make_float4(0.f, 0.f, 0.f, 0.f);
            float4 nv = hv;
            if (row < NN) {
                hv = ((const float4*)(h + (long long)row * DD))[c4];
                float inv = 1.0f / fmaxf(g_deg[row], 1.0f);
                float4 s = ((const float4*)(g_neigh + (long long)row * DD))[c4];
                nv = make_float4(s.x * inv, s.y * inv, s.z * inv, s.w * inv);
            }
            ((float4*)sh)[f] = hv;
            ((float4*)sn)[f] = nv;
        }
        __syncthreads();

        float acc[4][4];
        #pragma unroll
        for (int r = 0; r < 4; r++)
            #pragma unroll
            for (int c = 0; c < 4; c++) acc[r][c] = 0.f;

        int r0 = rg * 4;
        for (int k = 0; k < 128; k += 4) {
            float wa[4][4], wb[4][4];
            #pragma unroll
            for (int i = 0; i < 4; i++) {
                float4 x = *(const float4*)&sWs[(k + i) * 128 + c0];
                wa[i][0] = x.x; wa[i][1] = x.y; wa[i][2] = x.z; wa[i][3] = x.w;
                float4 y = *(const float4*)&sWn[(k + i) * 128 + c0];
                wb[i][0] = y.x; wb[i][1] = y.y; wb[i][2] = y.z; wb[i][3] = y.w;
            }
            #pragma unroll
            for (int r = 0; r < 4; r++) {
                float4 hx = *(const float4*)&sh[(r0 + r) * 128 + k];
                float4 nx = *(const float4*)&sn[(r0 + r) * 128 + k];
                float hv[4] = {hx.x, hx.y, hx.z, hx.w};
                float nv[4] = {nx.x, nx.y, nx.z, nx.w};
                #pragma unroll
                for (int i = 0; i < 4; i++)
                    #pragma unroll
                    for (int c = 0; c < 4; c++)
                        acc[r][c] += hv[i] * wa[i][c] + nv[i] * wb[i][c];
            }
        }

        // epilogue: bias, relu, stats, store
        #pragma unroll
        for (int r = 0; r < 4; r++) {
            int row = row_base + r0 + r;
            if (row < NN) {
                float v0 = fmaxf(acc[r][0] + bv.x, 0.f);
                float v1 = fmaxf(acc[r][1] + bv.y, 0.f);
                float v2 = fmaxf(acc[r][2] + bv.z, 0.f);
                float v3 = fmaxf(acc[r][3] + bv.w, 0.f);
                lsum[0] += v0; lsq[0] += v0 * v0;
                lsum[1] += v1; lsq[1] += v1 * v1;
                lsum[2] += v2; lsq[2] += v2 * v2;
                lsum[3] += v3; lsq[3] += v3 * v3;
                ((float4*)(g_rst + (long long)row * DD))[cg] =
                    make_float4(v0, v1, v2, v3);
            }
        }
    }

    // block reduction of column stats, then one atomic per column per stat
    __syncthreads();
    #pragma unroll
    for (int c = 0; c < 4; c++) {
        sred[rg * 128 + c0 + c]        = lsum[c];
        sred[1024 + rg * 128 + c0 + c] = lsq[c];
    }
    __syncthreads();
    {
        int stat = t >> 7;       // 0: sum, 1: sumsq
        int c    = t & 127;
        float s = 0.f;
        #pragma unroll
        for (int g = 0; g < 8; g++) s += sred[stat * 1024 + g * 128 + c];
        if (stat == 0) atomicAdd(&g_colsum[c], s);
        else           atomicAdd(&g_colsumsq[c], s);
    }
}

// ---------------------------------------------------------------------------
// K3: finalize BN coefficients: out = h + rst*A + B
// ---------------------------------------------------------------------------
__global__ void finalize_kernel(const float* __restrict__ gamma,
                                const float* __restrict__ beta) {
    int c = threadIdx.x;
    const float invN = 1.0f / (float)NN;
    float mean = g_colsum[c] * invN;
    float var  = g_colsumsq[c] * invN - mean * mean;
    float a = gamma[c] * rsqrtf(var + EPS);
    g_coefA[c] = a;
    g_coefB[c] = beta[c] - mean * a;
}

// ---------------------------------------------------------------------------
// K4: out = h + rst * A[c] + B[c]
// ---------------------------------------------------------------------------
__global__ void output_kernel(const float* __restrict__ h,
                              float* __restrict__ out) {
    int i = blockIdx.x * blockDim.x + threadIdx.x;
    int stride = gridDim.x * blockDim.x;
    const int nf4 = NN * DD / 4;
    for (int f = i; f < nf4; f += stride) {
        int cg = f & 31;
        float4 a  = ((const float4*)g_coefA)[cg];
        float4 bb = ((const float4*)g_coefB)[cg];
        float4 hv = ((const float4*)h)[f];
        float4 rv = ((const float4*)g_rst)[f];
        float4 o;
        o.x = hv.x + rv.x * a.x + bb.x;
        o.y = hv.y + rv.y * a.y + bb.y;
        o.z = hv.z + rv.z * a.z + bb.z;
        o.w = hv.w + rv.w * a.w + bb.w;
        ((float4*)out)[f] = o;
    }
}

// ---------------------------------------------------------------------------
extern "C" void kernel_launch(void* const* d_in, const int* in_sizes, int n_in,
                              void* d_out, int out_size) {
    const float* h      = (const float*)d_in[0];
    const int*   src    = (const int*)d_in[1];
    const int*   dst    = (const int*)d_in[2];
    const float* Wself  = (const float*)d_in[3];
    const float* Wneigh = (const float*)d_in[4];
    const float* bias   = (const float*)d_in[5];
    const float* gamma  = (const float*)d_in[6];
    const float* beta   = (const float*)d_in[7];
    float*       out    = (float*)d_out;

    zero_kernel<<<1024, 256>>>();
    scatter_kernel<<<14800, 256>>>(h, src, dst);

    const int smem_bytes = 43008 * 4;  // 172032
    cudaFuncSetAttribute(gemm_kernel,
                         cudaFuncAttributeMaxDynamicSharedMemorySize,
                         smem_bytes);
    gemm_kernel<<<(NN + RB - 1) / RB, 256, smem_bytes>>>(h, Wself, Wneigh, bias);

    finalize_kernel<<<1, DD>>>(gamma, beta);
    output_kernel<<<2048, 256>>>(h, out);
}

// round 3
// speedup vs baseline: 1.0429x; 1.0429x over previous
#include <cuda_runtime.h>

#define NN 100000
#define EE 3200000
#define DD 128
#define EPS 1e-5f

#define RB 64   // rows per GEMM block
#define TR 32   // rows per tile
#define SCAT_BLOCKS 4000
#define SELF_BLOCKS ((NN + RB - 1) / RB)   // 1563

// Scratch (allocation-free rule: __device__ globals)
__device__ float g_neigh[NN * DD];   // segment sums
__device__ float g_rst[NN * DD];     // h@Ws + b, then post-relu activations
__device__ float g_deg[NN];
__device__ float g_colsum[DD];
__device__ float g_colsumsq[DD];
__device__ float g_coefA[DD];
__device__ float g_coefB[DD];

// ---------------------------------------------------------------------------
// K0: zero scratch
// ---------------------------------------------------------------------------
__global__ void zero_kernel() {
    int i = blockIdx.x * blockDim.x + threadIdx.x;
    int stride = gridDim.x * blockDim.x;
    float4 z = make_float4(0.f, 0.f, 0.f, 0.f);
    float4* p = (float4*)g_neigh;
    const int nf4 = NN * DD / 4;
    for (int f = i; f < nf4; f += stride) p[f] = z;
    for (int f = i; f < NN; f += stride) g_deg[f] = 0.f;
    if (i < DD) { g_colsum[i] = 0.f; g_colsumsq[i] = 0.f; }
}

// ---------------------------------------------------------------------------
// K1 (fused): blocks [0, SCAT_BLOCKS) scatter edges with red.global.add.v4;
// blocks [SCAT_BLOCKS, ...) compute g_rst = h @ W_self + b.
// The self-GEMM FMA work hides under the scatter's memory stalls.
// ---------------------------------------------------------------------------
__global__ void __launch_bounds__(256, 2)
fused_scatter_self(const float* __restrict__ h,
                   const int* __restrict__ src,
                   const int* __restrict__ dst,
                   const float* __restrict__ Wself,
                   const float* __restrict__ bias) {
    extern __shared__ float sm[];

    if (blockIdx.x < SCAT_BLOCKS) {
        // ----- scatter role -----
        int lane = threadIdx.x & 31;
        int warp = (blockIdx.x * 256 + threadIdx.x) >> 5;
        const int nwarp = (SCAT_BLOCKS * 256) >> 5;      // 32000
        for (int e = warp * 2; e < EE; e += nwarp * 2) {
            int e1 = e + 1;
            int s0 = __ldg(&src[e]);
            int d0 = __ldg(&dst[e]);
            float4 v0 = ((const float4*)(h + (long long)s0 * DD))[lane];
            float4* p0 = ((float4*)(g_neigh + (long long)d0 * DD)) + lane;
            if (e1 < EE) {
                int s1 = __ldg(&src[e1]);
                int d1 = __ldg(&dst[e1]);
                float4 v1 = ((const float4*)(h + (long long)s1 * DD))[lane];
                float4* p1 = ((float4*)(g_neigh + (long long)d1 * DD)) + lane;
                asm volatile("red.global.add.v4.f32 [%0], {%1,%2,%3,%4};"
                             :: "l"(p0), "f"(v0.x), "f"(v0.y), "f"(v0.z), "f"(v0.w)
                             : "memory");
                asm volatile("red.global.add.v4.f32 [%0], {%1,%2,%3,%4};"
                             :: "l"(p1), "f"(v1.x), "f"(v1.y), "f"(v1.z), "f"(v1.w)
                             : "memory");
                if (lane == 0) {
                    atomicAdd(&g_deg[d0], 1.0f);
                    atomicAdd(&g_deg[d1], 1.0f);
                }
            } else {
                asm volatile("red.global.add.v4.f32 [%0], {%1,%2,%3,%4};"
                             :: "l"(p0), "f"(v0.x), "f"(v0.y), "f"(v0.z), "f"(v0.w)
                             : "memory");
                if (lane == 0) atomicAdd(&g_deg[d0], 1.0f);
            }
        }
        return;
    }

    // ----- self-GEMM role: g_rst = h @ Ws + b -----
    float* sWs = sm;            // 16384 floats (64 KB)
    float* sh  = sm + 16384;    // 4096 floats (16 KB)

    int t  = threadIdx.x;
    int cg = t & 31;
    int rg = t >> 5;
    int c0 = cg * 4;
    int gb = blockIdx.x - SCAT_BLOCKS;

    {
        const float4* w1 = (const float4*)Wself;
        float4* s1 = (float4*)sWs;
        for (int f = t; f < 4096; f += 256) s1[f] = w1[f];
    }

    float4 bv = ((const float4*)bias)[cg];

    for (int tt = 0; tt < RB / TR; tt++) {
        int row_base = gb * RB + tt * TR;
        __syncthreads();
        for (int f = t; f < TR * 32; f += 256) {
            int r  = f >> 5;
            int c4 = f & 31;
            int row = row_base + r;
            float4 hv = make_float4(0.f, 0.f, 0.f, 0.f);
            if (row < NN)
                hv = ((const float4*)(h + (long long)row * DD))[c4];
            ((float4*)sh)[f] = hv;
        }
        __syncthreads();

        float acc[4][4];
        #pragma unroll
        for (int r = 0; r < 4; r++)
            #pragma unroll
            for (int c = 0; c < 4; c++) acc[r][c] = 0.f;

        int r0 = rg * 4;
        for (int k = 0; k < 128; k += 4) {
            float wa[4][4];
            #pragma unroll
            for (int i = 0; i < 4; i++) {
                float4 x = *(const float4*)&sWs[(k + i) * 128 + c0];
                wa[i][0] = x.x; wa[i][1] = x.y; wa[i][2] = x.z; wa[i][3] = x.w;
            }
            #pragma unroll
            for (int r = 0; r < 4; r++) {
                float4 hx = *(const float4*)&sh[(r0 + r) * 128 + k];
                float hv[4] = {hx.x, hx.y, hx.z, hx.w};
                #pragma unroll
                for (int i = 0; i < 4; i++)
                    #pragma unroll
                    for (int c = 0; c < 4; c++)
                        acc[r][c] += hv[i] * wa[i][c];
            }
        }

        #pragma unroll
        for (int r = 0; r < 4; r++) {
            int row = row_base + r0 + r;
            if (row < NN) {
                ((float4*)(g_rst + (long long)row * DD))[cg] =
                    make_float4(acc[r][0] + bv.x, acc[r][1] + bv.y,
                                acc[r][2] + bv.z, acc[r][3] + bv.w);
            }
        }
    }
}

// ---------------------------------------------------------------------------
// K2: rst = relu(g_rst + (g_neigh/deg) @ Wn); fused BN column stats.
// ---------------------------------------------------------------------------
__global__ void __launch_bounds__(256, 2)
neigh_gemm_kernel(const float* __restrict__ Wneigh) {
    extern __shared__ float sm[];
    float* sWn  = sm;                    // 16384 floats
    float* sn   = sm + 16384;            // 4096
    float* sred = sm + 16384 + 4096;     // 2048
    // total 22528 floats = 90112 bytes

    int t  = threadIdx.x;
    int cg = t & 31;
    int rg = t >> 5;
    int c0 = cg * 4;

    {
        const float4* w2 = (const float4*)Wneigh;
        float4* s2 = (float4*)sWn;
        for (int f = t; f < 4096; f += 256) s2[f] = w2[f];
    }

    float lsum[4] = {0.f, 0.f, 0.f, 0.f};
    float lsq[4]  = {0.f, 0.f, 0.f, 0.f};

    for (int tt = 0; tt < RB / TR; tt++) {
        int row_base = blockIdx.x * RB + tt * TR;
        __syncthreads();
        for (int f = t; f < TR * 32; f += 256) {
            int r  = f >> 5;
            int c4 = f & 31;
            int row = row_base + r;
            float4 nv = make_float4(0.f, 0.f, 0.f, 0.f);
            if (row < NN) {
                float inv = 1.0f / fmaxf(g_deg[row], 1.0f);
                float4 s = ((const float4*)(g_neigh + (long long)row * DD))[c4];
                nv = make_float4(s.x * inv, s.y * inv, s.z * inv, s.w * inv);
            }
            ((float4*)sn)[f] = nv;
        }
        __syncthreads();

        float acc[4][4];
        #pragma unroll
        for (int r = 0; r < 4; r++)
            #pragma unroll
            for (int c = 0; c < 4; c++) acc[r][c] = 0.f;

        int r0 = rg * 4;
        for (int k = 0; k < 128; k += 4) {
            float wb[4][4];
            #pragma unroll
            for (int i = 0; i < 4; i++) {
                float4 y = *(const float4*)&sWn[(k + i) * 128 + c0];
                wb[i][0] = y.x; wb[i][1] = y.y; wb[i][2] = y.z; wb[i][3] = y.w;
            }
            #pragma unroll
            for (int r = 0; r < 4; r++) {
                float4 nx = *(const float4*)&sn[(r0 + r) * 128 + k];
                float nv[4] = {nx.x, nx.y, nx.z, nx.w};
                #pragma unroll
                for (int i = 0; i < 4; i++)
                    #pragma unroll
                    for (int c = 0; c < 4; c++)
                        acc[r][c] += nv[i] * wb[i][c];
            }
        }

        #pragma unroll
        for (int r = 0; r < 4; r++) {
            int row = row_base + r0 + r;
            if (row < NN) {
                float4* rp = ((float4*)(g_rst + (long long)row * DD)) + cg;
                float4 sv = *rp;
                float v0 = fmaxf(acc[r][0] + sv.x, 0.f);
                float v1 = fmaxf(acc[r][1] + sv.y, 0.f);
                float v2 = fmaxf(acc[r][2] + sv.z, 0.f);
                float v3 = fmaxf(acc[r][3] + sv.w, 0.f);
                lsum[0] += v0; lsq[0] += v0 * v0;
                lsum[1] += v1; lsq[1] += v1 * v1;
                lsum[2] += v2; lsq[2] += v2 * v2;
                lsum[3] += v3; lsq[3] += v3 * v3;
                *rp = make_float4(v0, v1, v2, v3);
            }
        }
    }

    __syncthreads();
    #pragma unroll
    for (int c = 0; c < 4; c++) {
        sred[rg * 128 + c0 + c]        = lsum[c];
        sred[1024 + rg * 128 + c0 + c] = lsq[c];
    }
    __syncthreads();
    {
        int stat = t >> 7;
        int c    = t & 127;
        float s = 0.f;
        #pragma unroll
        for (int g = 0; g < 8; g++) s += sred[stat * 1024 + g * 128 + c];
        if (stat == 0) atomicAdd(&g_colsum[c], s);
        else           atomicAdd(&g_colsumsq[c], s);
    }
}

// ---------------------------------------------------------------------------
// K3: finalize BN coefficients
// ---------------------------------------------------------------------------
__global__ void finalize_kernel(const float* __restrict__ gamma,
                                const float* __restrict__ beta) {
    int c = threadIdx.x;
    const float invN = 1.0f / (float)NN;
    float mean = g_colsum[c] * invN;
    float var  = g_colsumsq[c] * invN - mean * mean;
    float a = gamma[c] * rsqrtf(var + EPS);
    g_coefA[c] = a;
    g_coefB[c] = beta[c] - mean * a;
}

// ---------------------------------------------------------------------------
// K4: out = h + rst * A[c] + B[c]
// ---------------------------------------------------------------------------
__global__ void output_kernel(const float* __restrict__ h,
                              float* __restrict__ out) {
    int i = blockIdx.x * blockDim.x + threadIdx.x;
    int stride = gridDim.x * blockDim.x;
    const int nf4 = NN * DD / 4;
    for (int f = i; f < nf4; f += stride) {
        int cg = f & 31;
        float4 a  = ((const float4*)g_coefA)[cg];
        float4 bb = ((const float4*)g_coefB)[cg];
        float4 hv = ((const float4*)h)[f];
        float4 rv = ((const float4*)g_rst)[f];
        float4 o;
        o.x = hv.x + rv.x * a.x + bb.x;
        o.y = hv.y + rv.y * a.y + bb.y;
        o.z = hv.z + rv.z * a.z + bb.z;
        o.w = hv.w + rv.w * a.w + bb.w;
        ((float4*)out)[f] = o;
    }
}

// ---------------------------------------------------------------------------
extern "C" void kernel_launch(void* const* d_in, const int* in_sizes, int n_in,
                              void* d_out, int out_size) {
    const float* h      = (const float*)d_in[0];
    const int*   src    = (const int*)d_in[1];
    const int*   dst    = (const int*)d_in[2];
    const float* Wself  = (const float*)d_in[3];
    const float* Wneigh = (const float*)d_in[4];
    const float* bias   = (const float*)d_in[5];
    const float* gamma  = (const float*)d_in[6];
    const float* beta   = (const float*)d_in[7];
    float*       out    = (float*)d_out;

    zero_kernel<<<2048, 256>>>();

    const int fused_smem = 20480 * 4;   // 81920 B: sWs + sh
    cudaFuncSetAttribute(fused_scatter_self,
                         cudaFuncAttributeMaxDynamicSharedMemorySize,
                         fused_smem);
    fused_scatter_self<<<SCAT_BLOCKS + SELF_BLOCKS, 256, fused_smem>>>(
        h, src, dst, Wself, bias);

    const int neigh_smem = 22528 * 4;   // 90112 B
    cudaFuncSetAttribute(neigh_gemm_kernel,
                         cudaFuncAttributeMaxDynamicSharedMemorySize,
                         neigh_smem);
    neigh_gemm_kernel<<<(NN + RB - 1) / RB, 256, neigh_smem>>>(Wneigh);

    finalize_kernel<<<1, DD>>>(gamma, beta);
    output_kernel<<<2048, 256>>>(h, out);
}